// round 6
// baseline (speedup 1.0000x reference)
#include <cuda_runtime.h>
#include <cuda_bf16.h>
#include <cstdint>

#define NNODES 100000
#define NEDGES 1600000
#define DIM    128

// Scratch: sum-aggregation buffer (re-used by both layers). 51.2 MB.
__device__ float g_agg[(size_t)NNODES * DIM];

// ---------------------------------------------------------------------------
// Kernel 1: zero the aggregation buffer (float4 grid-stride).
// ---------------------------------------------------------------------------
__global__ void zero_kernel(float4* __restrict__ p, int n4) {
    int i = blockIdx.x * blockDim.x + threadIdx.x;
    const float4 z = make_float4(0.f, 0.f, 0.f, 0.f);
    for (; i < n4; i += gridDim.x * blockDim.x) p[i] = z;
}

// ---------------------------------------------------------------------------
// Kernel 2: edge scatter-add. One warp per edge; lane l handles dims [4l,4l+4).
// src row is gathered as float4 (L2-resident), accumulated into agg[dst] with
// red.global.add.v4.f32 (no-return vector reduction, sm_90+).
// ---------------------------------------------------------------------------
__global__ void scatter_kernel(const float* __restrict__ x,
                               const int* __restrict__ edge_index) {
    int warp = (blockIdx.x * blockDim.x + threadIdx.x) >> 5;
    int lane = threadIdx.x & 31;
    if (warp >= NEDGES) return;
    int src = __ldg(edge_index + warp);           // row 0: src
    int dst = __ldg(edge_index + NEDGES + warp);  // row 1: dst

    const float4* xrow = reinterpret_cast<const float4*>(x + (size_t)src * DIM);
    float4 v = __ldg(xrow + lane);

    float* base = g_agg + (size_t)dst * DIM + lane * 4;
    asm volatile("red.global.add.v4.f32 [%0], {%1, %2, %3, %4};"
                 :: "l"(base), "f"(v.x), "f"(v.y), "f"(v.z), "f"(v.w)
                 : "memory");
}

// ---------------------------------------------------------------------------
// Kernel 3: fused (A + Agg) @ W^T + bias GEMM.
//   out[n][o] = bias[o] + sum_k (A[n][k] + Agg[n][k]) * W[o][k]
// Block: 256 threads, 64 nodes x 128 outs per block.
// Smem (dynamic, 96 KB): Wt[k][o] (transposed W) + inT[k][n] (transposed input).
// Each thread: 4 nodes x 8 outs = 32 fp32 accumulators; inner loop over k
// does 3x LDS.128 + 32 FMA -> FMA-issue-bound.
// ---------------------------------------------------------------------------
__global__ __launch_bounds__(256, 2)
void gemm_kernel(const float* __restrict__ A,
                 const float* __restrict__ Agg,
                 const float* __restrict__ W,
                 const float* __restrict__ bias,
                 float* __restrict__ out) {
    extern __shared__ float sm[];
    float* Wt  = sm;                 // [128][128]  Wt[k*128 + o]
    float* inT = sm + DIM * DIM;     // [128][64]   inT[k*64 + n]

    const int tid   = threadIdx.x;
    const int node0 = blockIdx.x * 64;

    // Load W transposed: W is [o][k] row-major. 128*128/4 = 4096 float4s.
    for (int i = tid; i < DIM * DIM / 4; i += 256) {
        int o = (i * 4) / DIM;
        int k = (i * 4) % DIM;
        float4 w = __ldg(reinterpret_cast<const float4*>(W) + i);
        Wt[(k + 0) * DIM + o] = w.x;
        Wt[(k + 1) * DIM + o] = w.y;
        Wt[(k + 2) * DIM + o] = w.z;
        Wt[(k + 3) * DIM + o] = w.w;
    }

    // Load input tile transposed with the (x + agg) add fused in.
    for (int i = tid; i < 64 * DIM / 4; i += 256) {
        int n = (i * 4) / DIM;
        int k = (i * 4) % DIM;
        int node = node0 + n;
        float4 a = make_float4(0.f, 0.f, 0.f, 0.f);
        float4 b = a;
        if (node < NNODES) {
            size_t gi = ((size_t)node * DIM + k) / 4;
            a = __ldg(reinterpret_cast<const float4*>(A) + gi);
            b = __ldg(reinterpret_cast<const float4*>(Agg) + gi);
        }
        inT[(k + 0) * 64 + n] = a.x + b.x;
        inT[(k + 1) * 64 + n] = a.y + b.y;
        inT[(k + 2) * 64 + n] = a.z + b.z;
        inT[(k + 3) * 64 + n] = a.w + b.w;
    }
    __syncthreads();

    const int tx = tid & 15;   // 16 output groups of 8
    const int ty = tid >> 4;   // 16 node groups of 4
    const int o0 = tx * 8;
    const int n0 = ty * 4;

    float acc[4][8];
#pragma unroll
    for (int j = 0; j < 8; ++j) {
        float bj = __ldg(bias + o0 + j);
#pragma unroll
        for (int i = 0; i < 4; ++i) acc[i][j] = bj;
    }

#pragma unroll 4
    for (int k = 0; k < DIM; ++k) {
        float4 av = *reinterpret_cast<const float4*>(&inT[k * 64 + n0]);
        float4 w0 = *reinterpret_cast<const float4*>(&Wt[k * DIM + o0]);
        float4 w1 = *reinterpret_cast<const float4*>(&Wt[k * DIM + o0 + 4]);
        float a4[4] = {av.x, av.y, av.z, av.w};
        float w8[8] = {w0.x, w0.y, w0.z, w0.w, w1.x, w1.y, w1.z, w1.w};
#pragma unroll
        for (int i = 0; i < 4; ++i)
#pragma unroll
            for (int j = 0; j < 8; ++j)
                acc[i][j] = fmaf(a4[i], w8[j], acc[i][j]);
    }

#pragma unroll
    for (int i = 0; i < 4; ++i) {
        int node = node0 + n0 + i;
        if (node < NNODES) {
            float4* orow = reinterpret_cast<float4*>(out + (size_t)node * DIM + o0);
            orow[0] = make_float4(acc[i][0], acc[i][1], acc[i][2], acc[i][3]);
            orow[1] = make_float4(acc[i][4], acc[i][5], acc[i][6], acc[i][7]);
        }
    }
}

// ---------------------------------------------------------------------------
// Launch: two GIN layers. Tuple output (out, hid):
//   d_out[0       : N*D) = out   (layer 2 result)
//   d_out[N*D : 2*N*D)   = hid   (layer 1 result; also layer-2 input)
// ---------------------------------------------------------------------------
extern "C" void kernel_launch(void* const* d_in, const int* in_sizes, int n_in,
                              void* d_out, int out_size) {
    const float* x  = (const float*)d_in[0];
    const int*   ei = (const int*)  d_in[1];
    const float* W1 = (const float*)d_in[2];
    const float* b1 = (const float*)d_in[3];
    const float* W2 = (const float*)d_in[4];
    const float* b2 = (const float*)d_in[5];

    float* out = (float*)d_out;                       // [N, D]
    float* hid = (float*)d_out + (size_t)NNODES * DIM; // [N, D]

    static bool attr_set = false;
    if (!attr_set) {
        cudaFuncSetAttribute(gemm_kernel,
                             cudaFuncAttributeMaxDynamicSharedMemorySize,
                             (DIM * DIM + DIM * 64) * (int)sizeof(float));
        attr_set = true;
    }

    float* agg;
    cudaGetSymbolAddress((void**)&agg, g_agg);

    const int n4 = NNODES * DIM / 4;                  // 3.2M float4s
    const int zero_blocks = 2048;
    const int scat_blocks = (NEDGES * 32 + 255) / 256; // 1 warp/edge, 256 thr/blk
    const int gemm_blocks = (NNODES + 63) / 64;
    const int smem = (DIM * DIM + DIM * 64) * (int)sizeof(float); // 96 KB

    // ---- Layer 1 ----
    zero_kernel<<<zero_blocks, 256>>>((float4*)agg, n4);
    scatter_kernel<<<scat_blocks, 256>>>(x, ei);
    gemm_kernel<<<gemm_blocks, 256, smem>>>(x, agg, W1, b1, hid);

    // ---- Layer 2 ----
    zero_kernel<<<zero_blocks, 256>>>((float4*)agg, n4);
    scatter_kernel<<<scat_blocks, 256>>>(hid, ei);
    gemm_kernel<<<gemm_blocks, 256, smem>>>(hid, agg, W2, b2, out);
}

// round 7
// speedup vs baseline: 1.4950x; 1.4950x over previous
#include <cuda_runtime.h>
#include <cuda_bf16.h>
#include <cstdint>

#define NNODES 100000
#define NEDGES 1600000
#define DIM    128
#define SCANB  1024
#define NBLK   ((NNODES + SCANB - 1) / SCANB)   // 98

typedef unsigned long long u64;

// ---------------- scratch (alloc-free rule: __device__ globals) -------------
__device__ float g_agg[(size_t)NNODES * DIM];   // h = x_i + sum_j x_j
__device__ int   g_deg[NNODES];
__device__ int   g_incl[NNODES];
__device__ int   g_off[NNODES + 1];
__device__ int   g_cur[NNODES];
__device__ int   g_csr[NEDGES];
__device__ int   g_bsum[128];
__device__ int   g_bofs[128];

// ---------------------------------------------------------------------------
// CSR build: deg histogram -> exclusive scan -> fill src lists per dst.
// ---------------------------------------------------------------------------
__global__ void zero_deg_kernel() {
    int i = blockIdx.x * blockDim.x + threadIdx.x;
    if (i < NNODES) g_deg[i] = 0;
}

__global__ void hist_kernel(const int* __restrict__ ei) {
    int e = blockIdx.x * blockDim.x + threadIdx.x;
    if (e < NEDGES) atomicAdd(&g_deg[__ldg(ei + NEDGES + e)], 1);
}

__global__ void scan1_kernel() {            // NBLK blocks x 1024 threads
    __shared__ int sm[SCANB];
    int i = blockIdx.x * SCANB + threadIdx.x;
    int v = (i < NNODES) ? g_deg[i] : 0;
    sm[threadIdx.x] = v;
    __syncthreads();
#pragma unroll
    for (int ofs = 1; ofs < SCANB; ofs <<= 1) {
        int t = (threadIdx.x >= ofs) ? sm[threadIdx.x - ofs] : 0;
        __syncthreads();
        sm[threadIdx.x] += t;
        __syncthreads();
    }
    if (i < NNODES) g_incl[i] = sm[threadIdx.x];
    if (threadIdx.x == SCANB - 1) g_bsum[blockIdx.x] = sm[SCANB - 1];
}

__global__ void scan2_kernel() {            // 1 block x 128 threads
    __shared__ int sm[128];
    int t = threadIdx.x;
    int v = (t < NBLK) ? g_bsum[t] : 0;
    sm[t] = v;
    __syncthreads();
#pragma unroll
    for (int ofs = 1; ofs < 128; ofs <<= 1) {
        int u = (t >= ofs) ? sm[t - ofs] : 0;
        __syncthreads();
        sm[t] += u;
        __syncthreads();
    }
    if (t < NBLK) g_bofs[t] = sm[t] - v;    // exclusive
}

__global__ void scan3_kernel() {
    int i = blockIdx.x * blockDim.x + threadIdx.x;
    if (i < NNODES) {
        int off = g_incl[i] - g_deg[i] + g_bofs[i >> 10];
        g_off[i] = off;
        g_cur[i] = off;
    }
    if (i == 0) g_off[NNODES] = NEDGES;
}

__global__ void fill_kernel(const int* __restrict__ ei) {
    int e = blockIdx.x * blockDim.x + threadIdx.x;
    if (e < NEDGES) {
        int dst = __ldg(ei + NEDGES + e);
        int p = atomicAdd(&g_cur[dst], 1);
        g_csr[p] = __ldg(ei + e);
    }
}

// ---------------------------------------------------------------------------
// Aggregation: one warp per destination node. Lane l owns dims [4l,4l+4).
// acc = x_i + sum over in-edges of x[src]. Zero atomics; L2-resident gather.
// ---------------------------------------------------------------------------
__global__ __launch_bounds__(256)
void agg_kernel(const float* __restrict__ x) {
    int w    = (blockIdx.x * blockDim.x + threadIdx.x) >> 5;
    int lane = threadIdx.x & 31;
    if (w >= NNODES) return;

    const float4* X = reinterpret_cast<const float4*>(x);
    int s = g_off[w];
    int e = g_off[w + 1];

    float4 acc = __ldg(X + (size_t)w * 32 + lane);   // (1+eps)*x_i, eps=0

    for (int base = s; base < e; base += 32) {
        int idx = base + lane;
        int my  = (idx < e) ? __ldg(g_csr + idx) : 0;
        int nv  = min(32, e - base);
#pragma unroll 4
        for (int j = 0; j < nv; ++j) {
            int src  = __shfl_sync(0xffffffffu, my, j);
            float4 v = __ldg(X + (size_t)src * 32 + lane);
            acc.x += v.x; acc.y += v.y; acc.z += v.z; acc.w += v.w;
        }
    }
    reinterpret_cast<float4*>(g_agg)[(size_t)w * 32 + lane] = acc;
}

// ---------------------------------------------------------------------------
// GEMM: out[n][o] = bias[o] + sum_k H[n][k] * W[o][k]  using packed f32x2 FMA
// (2 outputs per 64-bit accumulator -> half the fma-pipe issue slots).
// Block: 256 thr, 64 nodes x 128 outs; smem: Wt[k][o] 64KB + HT[k][n] 32KB.
// ---------------------------------------------------------------------------
__device__ __forceinline__ u64 ffma2(u64 a, u64 b, u64 c) {
    u64 d;
    asm("fma.rn.f32x2 %0, %1, %2, %3;" : "=l"(d) : "l"(a), "l"(b), "l"(c));
    return d;
}
__device__ __forceinline__ u64 pk2(float lo, float hi) {
    u64 r;
    asm("mov.b64 %0, {%1, %2};" : "=l"(r) : "f"(lo), "f"(hi));
    return r;
}

__global__ __launch_bounds__(256, 2)
void gemm_kernel(const float* __restrict__ H,
                 const float* __restrict__ W,
                 const float* __restrict__ bias,
                 float* __restrict__ out) {
    extern __shared__ float sm[];
    float* Wt = sm;               // [128][128]  Wt[k*128 + o]
    float* HT = sm + DIM * DIM;   // [128][64]   HT[k*64 + n]

    const int tid   = threadIdx.x;
    const int node0 = blockIdx.x * 64;

    // W [o][k] row-major -> Wt[k][o]
    for (int i = tid; i < DIM * DIM / 4; i += 256) {
        int o = (i * 4) / DIM;
        int k = (i * 4) % DIM;
        float4 w = __ldg(reinterpret_cast<const float4*>(W) + i);
        Wt[(k + 0) * DIM + o] = w.x;
        Wt[(k + 1) * DIM + o] = w.y;
        Wt[(k + 2) * DIM + o] = w.z;
        Wt[(k + 3) * DIM + o] = w.w;
    }
    // H tile transposed
    for (int i = tid; i < 64 * DIM / 4; i += 256) {
        int n = (i * 4) / DIM;
        int k = (i * 4) % DIM;
        int node = node0 + n;
        float4 h = make_float4(0.f, 0.f, 0.f, 0.f);
        if (node < NNODES)
            h = __ldg(reinterpret_cast<const float4*>(H) + ((size_t)node * DIM + k) / 4);
        HT[(k + 0) * 64 + n] = h.x;
        HT[(k + 1) * 64 + n] = h.y;
        HT[(k + 2) * 64 + n] = h.z;
        HT[(k + 3) * 64 + n] = h.w;
    }
    __syncthreads();

    const int tx = tid & 15;      // 16 output groups of 8 (= 4 pairs)
    const int ty = tid >> 4;      // 16 node groups of 4
    const int o0 = tx * 8;
    const int n0 = ty * 4;

    // acc[i][j] = packed outputs (o0+2j, o0+2j+1) for node n0+i
    u64 acc[4][4];
    {
        float4 b0 = __ldg(reinterpret_cast<const float4*>(bias + o0));
        float4 b1 = __ldg(reinterpret_cast<const float4*>(bias + o0 + 4));
        u64 bp[4] = { pk2(b0.x, b0.y), pk2(b0.z, b0.w),
                      pk2(b1.x, b1.y), pk2(b1.z, b1.w) };
#pragma unroll
        for (int i = 0; i < 4; ++i)
#pragma unroll
            for (int j = 0; j < 4; ++j) acc[i][j] = bp[j];
    }

#pragma unroll 4
    for (int k = 0; k < DIM; ++k) {
        float4 av = *reinterpret_cast<const float4*>(&HT[k * 64 + n0]);
        float4 w0 = *reinterpret_cast<const float4*>(&Wt[k * DIM + o0]);
        float4 w1 = *reinterpret_cast<const float4*>(&Wt[k * DIM + o0 + 4]);
        u64 wp[4] = { pk2(w0.x, w0.y), pk2(w0.z, w0.w),
                      pk2(w1.x, w1.y), pk2(w1.z, w1.w) };
        u64 ap[4] = { pk2(av.x, av.x), pk2(av.y, av.y),
                      pk2(av.z, av.z), pk2(av.w, av.w) };
#pragma unroll
        for (int i = 0; i < 4; ++i)
#pragma unroll
            for (int j = 0; j < 4; ++j)
                acc[i][j] = ffma2(ap[i], wp[j], acc[i][j]);
    }

#pragma unroll
    for (int i = 0; i < 4; ++i) {
        int node = node0 + n0 + i;
        if (node < NNODES) {
            ulonglong2* orow = reinterpret_cast<ulonglong2*>(out + (size_t)node * DIM + o0);
            orow[0] = make_ulonglong2(acc[i][0], acc[i][1]);
            orow[1] = make_ulonglong2(acc[i][2], acc[i][3]);
        }
    }
}

// ---------------------------------------------------------------------------
// Launch. Output tuple (out, hid): d_out[0:N*D)=out, d_out[N*D:2N*D)=hid.
// ---------------------------------------------------------------------------
extern "C" void kernel_launch(void* const* d_in, const int* in_sizes, int n_in,
                              void* d_out, int out_size) {
    const float* x  = (const float*)d_in[0];
    const int*   ei = (const int*)  d_in[1];
    const float* W1 = (const float*)d_in[2];
    const float* b1 = (const float*)d_in[3];
    const float* W2 = (const float*)d_in[4];
    const float* b2 = (const float*)d_in[5];

    float* out = (float*)d_out;
    float* hid = (float*)d_out + (size_t)NNODES * DIM;

    static bool attr_set = false;
    if (!attr_set) {
        cudaFuncSetAttribute(gemm_kernel,
                             cudaFuncAttributeMaxDynamicSharedMemorySize,
                             (DIM * DIM + DIM * 64) * (int)sizeof(float));
        attr_set = true;
    }

    float* agg;
    cudaGetSymbolAddress((void**)&agg, g_agg);

    const int nb_nodes = (NNODES + 255) / 256;
    const int nb_edges = (NEDGES + 255) / 256;
    const int nb_agg   = (NNODES * 32 + 255) / 256;   // 1 warp/node
    const int nb_gemm  = (NNODES + 63) / 64;
    const int smem     = (DIM * DIM + DIM * 64) * (int)sizeof(float);

    // ---- CSR build (once; shared by both layers) ----
    zero_deg_kernel<<<nb_nodes, 256>>>();
    hist_kernel<<<nb_edges, 256>>>(ei);
    scan1_kernel<<<NBLK, SCANB>>>();
    scan2_kernel<<<1, 128>>>();
    scan3_kernel<<<nb_nodes, 256>>>();
    fill_kernel<<<nb_edges, 256>>>(ei);

    // ---- Layer 1 ----
    agg_kernel<<<nb_agg, 256>>>(x);
    gemm_kernel<<<nb_gemm, 256, smem>>>(agg, W1, b1, hid);

    // ---- Layer 2 ----
    agg_kernel<<<nb_agg, 256>>>(hid);
    gemm_kernel<<<nb_gemm, 256, smem>>>(agg, W2, b2, out);
}